// round 12
// baseline (speedup 1.0000x reference)
#include <cuda_runtime.h>

// VoxelMorph SpatialTransformer, trilinear, zero padding.
// Smem-tiled gather v7: 16x8x32 tile (110.4KB, 2 CTAs/SM, 1024 thr), each
// thread owns 2 x-adjacent voxels => float2 flow loads / out stores, 2x
// memory ILP. Streaming cache hints keep src L2-resident. Vectorized fill,
// channel-interleaved float2 smem, int32 indexing, reference-exact rounding.
// src:  [B=2, C=2, 160, 192, 160] f32
// flow: [B=2, 3,   160, 192, 160] f32  (dz, dy, dx)
// out:  [B=2, C=2, 160, 192, 160] f32

namespace {
constexpr int D = 160, H = 192, W = 160, C = 2, B = 2;
constexpr int N  = D * H * W;
constexpr int HW = H * W;

constexpr int TZ = 16, TY = 8, TX = 32; // output tile (4096 voxels)
constexpr int R  = 3;
constexpr int SZ = TZ + 1 + 2 * R;      // 23
constexpr int SY = TY + 1 + 2 * R;      // 15
constexpr int SXP = 40;                 // x entries (float2), quad-aligned
constexpr int ROWS = SZ * SY;           // 345
constexpr int QPR  = SXP / 4;           // 10
constexpr int SMEM_BYTES = ROWS * SXP * 8;   // 110400
constexpr int NZT = D / TZ;             // 10
constexpr int ZPT = 2;                  // z-planes per thread (8 z thread-groups)
constexpr int NTHREADS = 1024;
// smem x coordinate: x' = gx - (x_t - 4); valid gather x' in [1, 38]
}

// gather one voxel from the smem tile (or global fallback); returns (ch0, ch1)
__device__ __forceinline__ float2 gather_one(
    const float2* __restrict__ sm2,
    const float* __restrict__ s0, const float* __restrict__ s1,
    float zf, float yf, float xf,
    int z_lo, int y_lo, int x_al)
{
    const int z0 = __float2int_rd(zf);
    const int y0 = __float2int_rd(yf);
    const int x0 = __float2int_rd(xf);
    const float fz = zf - (float)z0;
    const float fy = yf - (float)y0;
    const float fx = xf - (float)x0;
    const float gz = 1.0f - fz, gy = 1.0f - fy, gx = 1.0f - fx;

    const float w00 = gz * gy, w01 = gz * fy, w10 = fz * gy, w11 = fz * fy;
    const float w000 = w00 * gx, w001 = w00 * fx;
    const float w010 = w01 * gx, w011 = w01 * fx;
    const float w100 = w10 * gx, w101 = w10 * fx;
    const float w110 = w11 * gx, w111 = w11 * fx;

    const int z0l = z0 - z_lo;
    const int y0l = y0 - y_lo;
    const int x0l = x0 - x_al;

    float a0, a1;
    if (((unsigned)z0l <= (unsigned)(SZ - 2)) &
        ((unsigned)y0l <= (unsigned)(SY - 2)) &
        ((unsigned)(x0l - 1) <= (unsigned)(SXP - 3))) {
        const float2* p = sm2 + (z0l * SY + y0l) * SXP + x0l;
        const float2 c000 = p[0];
        const float2 c001 = p[1];
        const float2 c010 = p[SXP];
        const float2 c011 = p[SXP + 1];
        const float2 c100 = p[SY * SXP];
        const float2 c101 = p[SY * SXP + 1];
        const float2 c110 = p[SY * SXP + SXP];
        const float2 c111 = p[SY * SXP + SXP + 1];
        a0 = w000 * c000.x + w001 * c001.x
           + w010 * c010.x + w011 * c011.x
           + w100 * c100.x + w101 * c101.x
           + w110 * c110.x + w111 * c111.x;
        a1 = w000 * c000.y + w001 * c001.y
           + w010 * c010.y + w011 * c011.y
           + w100 * c100.y + w101 * c101.y
           + w110 * c110.y + w111 * c111.y;
    } else {
        a0 = 0.0f; a1 = 0.0f;
        #pragma unroll
        for (int dz = 0; dz < 2; ++dz) {
            const int zi = z0 + dz;
            if ((unsigned)zi >= (unsigned)D) continue;
            const float wz = dz ? fz : gz;
            #pragma unroll
            for (int dy = 0; dy < 2; ++dy) {
                const int yi = y0 + dy;
                if ((unsigned)yi >= (unsigned)H) continue;
                const float wzy = wz * (dy ? fy : gy);
                #pragma unroll
                for (int dx = 0; dx < 2; ++dx) {
                    const int xi = x0 + dx;
                    if ((unsigned)xi >= (unsigned)W) continue;
                    const float wgt = wzy * (dx ? fx : gx);
                    const int lin = (zi * H + yi) * W + xi;
                    a0 += wgt * __ldg(s0 + lin);
                    a1 += wgt * __ldg(s1 + lin);
                }
            }
        }
    }
    return make_float2(a0, a1);
}

__global__ __launch_bounds__(NTHREADS, 2)
void st_v11_kernel(const float* __restrict__ src,
                   const float* __restrict__ flow,
                   float* __restrict__ out)
{
    extern __shared__ float2 sm2[];     // [SZ*SY][SXP], .x=ch0 .y=ch1

    const int bzz = blockIdx.z;
    const int b   = bzz / NZT;
    const int z_t = (bzz - b * NZT) * TZ;
    const int y_t = blockIdx.y * TY;
    const int x_t = blockIdx.x * TX;
    const int z_lo = z_t - R, y_lo = y_t - R;
    const int x_al = x_t - 4;           // smem x' = gx - x_al

    const int tid = (threadIdx.z * TY + threadIdx.y) * 16 + threadIdx.x;

    const float* s0 = src + b * C * N;
    const float* s1 = s0 + N;

    // ---- fill: (row, quad) units, all-or-nothing quad validity ----
    for (int u = tid; u < ROWS * QPR; u += NTHREADS) {
        const int row = u / QPR;
        const int qi  = u - row * QPR;
        const int sz  = row / SY;
        const int sy  = row - sz * SY;
        const int gz  = z_lo + sz;
        const int gy  = y_lo + sy;
        const int gx  = x_al + 4 * qi;  // multiple of 4
        float4 q0 = make_float4(0.f, 0.f, 0.f, 0.f);
        float4 q1 = q0;
        if (((unsigned)gz < (unsigned)D) & ((unsigned)gy < (unsigned)H) &
            ((unsigned)gx < (unsigned)W)) {
            const int off = (gz * H + gy) * W + gx;
            q0 = __ldg((const float4*)(s0 + off));
            q1 = __ldg((const float4*)(s1 + off));
        }
        float4* dst = (float4*)(sm2 + row * SXP + 4 * qi);
        dst[0] = make_float4(q0.x, q1.x, q0.y, q1.y);
        dst[1] = make_float4(q0.z, q1.z, q0.w, q1.w);
    }
    __syncthreads();

    // ---- gather: each thread owns 2 x-adjacent voxels, ZPT z-planes ----
    const int h  = y_t + threadIdx.y;
    const int w0 = x_t + threadIdx.x * 2;       // even
    const int z_b = z_t + threadIdx.z * ZPT;

    const float* fb = flow + b * 3 * N;
    float* ob = out + b * C * N;

    int s = (z_b * H + h) * W + w0;             // 8B-aligned (w0 even)

    #pragma unroll
    for (int k = 0; k < ZPT; ++k, s += HW) {
        const int d = z_b + k;

        const float2 f2z = __ldcs((const float2*)(fb + s));
        const float2 f2y = __ldcs((const float2*)(fb + s + N));
        const float2 f2x = __ldcs((const float2*)(fb + s + 2 * N));

        const float2 r0 = gather_one(sm2, s0, s1,
                                     (float)d + f2z.x,
                                     (float)h + f2y.x,
                                     (float)w0 + f2x.x,
                                     z_lo, y_lo, x_al);
        const float2 r1 = gather_one(sm2, s0, s1,
                                     (float)d + f2z.y,
                                     (float)h + f2y.y,
                                     (float)(w0 + 1) + f2x.y,
                                     z_lo, y_lo, x_al);

        __stcs((float2*)(ob + s),     make_float2(r0.x, r1.x));  // ch0
        __stcs((float2*)(ob + s + N), make_float2(r0.y, r1.y));  // ch1
    }
}

extern "C" void kernel_launch(void* const* d_in, const int* in_sizes, int n_in,
                              void* d_out, int out_size)
{
    const float* src  = (const float*)d_in[0];
    const float* flow = (const float*)d_in[1];
    float* out = (float*)d_out;

    static bool attr_done = false;
    if (!attr_done) {
        cudaFuncSetAttribute(st_v11_kernel,
                             cudaFuncAttributeMaxDynamicSharedMemorySize,
                             SMEM_BYTES);
        attr_done = true;
    }

    dim3 block(16, TY, 8);                  // 1024 threads
    dim3 grid(W / TX, H / TY, B * NZT);     // 5, 24, 20
    st_v11_kernel<<<grid, block, SMEM_BYTES>>>(src, flow, out);
}

// round 14
// speedup vs baseline: 1.6176x; 1.6176x over previous
#include <cuda_runtime.h>
#include <cuda_fp16.h>

// VoxelMorph SpatialTransformer, trilinear, zero padding.
// Smem-tiled gather v8b: corners stored as __half2 (ch0,ch1) => 1 LDS.32 per
// corner (half the bytes, half the bank conflicts of float2), enabling a
// 16x16x32 tile (84.6KB, 2x1024-thread CTAs/SM) with fill amplification 2.58x.
// Weights and accumulation stay fp32; boundary fallback reads exact fp32 src.
// src:  [B=2, C=2, 160, 192, 160] f32
// flow: [B=2, 3,   160, 192, 160] f32  (dz, dy, dx)
// out:  [B=2, C=2, 160, 192, 160] f32

namespace {
constexpr int D = 160, H = 192, W = 160, C = 2, B = 2;
constexpr int N  = D * H * W;
constexpr int HW = H * W;

constexpr int TZ = 16, TY = 16, TX = 32;  // output tile (8192 voxels)
constexpr int R  = 3;
constexpr int SZ = TZ + 1 + 2 * R;        // 23 z-slices
constexpr int SY = TY + 1 + 2 * R;        // 23 y-rows
constexpr int SXP = 40;                   // x entries (half2), quad-aligned
constexpr int ROWS = SZ * SY;             // 529
constexpr int QPR  = SXP / 4;             // 10 quads per row
constexpr int SMEM_BYTES = ROWS * SXP * 4;    // 84640
constexpr int NZT = D / TZ;               // 10
constexpr int ZPT = 8;                    // z-planes per thread (2 z thread-groups)
constexpr int NTHREADS = 1024;
// smem x coordinate: x' = gx - (x_t - 4); valid gather x' in [1, 38]
}

__device__ __forceinline__ unsigned h2_bits(__half2 h) {
    return *reinterpret_cast<unsigned*>(&h);
}

__global__ __launch_bounds__(NTHREADS, 2)
void st_v12_kernel(const float* __restrict__ src,
                   const float* __restrict__ flow,
                   float* __restrict__ out)
{
    extern __shared__ __half2 smh[];      // [SZ*SY][SXP], (ch0, ch1)

    const int bzz = blockIdx.z;
    const int b   = bzz / NZT;
    const int z_t = (bzz - b * NZT) * TZ;
    const int y_t = blockIdx.y * TY;
    const int x_t = blockIdx.x * TX;
    const int z_lo = z_t - R, y_lo = y_t - R;
    const int x_al = x_t - 4;             // smem x' = gx - x_al

    const int tid = (threadIdx.z * TY + threadIdx.y) * TX + threadIdx.x;

    const float* s0 = src + b * C * N;
    const float* s1 = s0 + N;

    // ---- fill: (row, quad) units; 2x LDG.128 -> 4x half2 -> 1x STS.128 ----
    for (int u = tid; u < ROWS * QPR; u += NTHREADS) {
        const int row = u / QPR;
        const int qi  = u - row * QPR;
        const int sz  = row / SY;
        const int sy  = row - sz * SY;
        const int gz  = z_lo + sz;
        const int gy  = y_lo + sy;
        const int gx  = x_al + 4 * qi;    // multiple of 4
        float4 q0 = make_float4(0.f, 0.f, 0.f, 0.f);
        float4 q1 = q0;
        if (((unsigned)gz < (unsigned)D) & ((unsigned)gy < (unsigned)H) &
            ((unsigned)gx < (unsigned)W)) {
            const int off = (gz * H + gy) * W + gx;   // 16B-aligned
            q0 = __ldg((const float4*)(s0 + off));
            q1 = __ldg((const float4*)(s1 + off));
        }
        const __half2 h0 = __floats2half2_rn(q0.x, q1.x);
        const __half2 h1 = __floats2half2_rn(q0.y, q1.y);
        const __half2 h2 = __floats2half2_rn(q0.z, q1.z);
        const __half2 h3 = __floats2half2_rn(q0.w, q1.w);
        const uint4 packed = make_uint4(h2_bits(h0), h2_bits(h1),
                                        h2_bits(h2), h2_bits(h3));
        *((uint4*)(smh + row * SXP + 4 * qi)) = packed;     // 16B-aligned
    }
    __syncthreads();

    // ---- gather: each thread handles ZPT z-planes ----
    const int h = y_t + threadIdx.y;
    const int w = x_t + threadIdx.x;
    const int z_b = z_t + threadIdx.z * ZPT;

    const float* fb = flow + b * 3 * N;
    float* ob = out + b * C * N;

    int s = (z_b * H + h) * W + w;

    #pragma unroll 4
    for (int k = 0; k < ZPT; ++k, s += HW) {
        const int d = z_b + k;

        const float zf = (float)d + __ldcs(fb + s);
        const float yf = (float)h + __ldcs(fb + s + N);
        const float xf = (float)w + __ldcs(fb + s + 2 * N);

        const int z0 = __float2int_rd(zf);
        const int y0 = __float2int_rd(yf);
        const int x0 = __float2int_rd(xf);
        const float fz = zf - (float)z0;
        const float fy = yf - (float)y0;
        const float fx = xf - (float)x0;
        const float gz = 1.0f - fz, gy = 1.0f - fy, gx = 1.0f - fx;

        const float w00 = gz * gy, w01 = gz * fy, w10 = fz * gy, w11 = fz * fy;
        const float w000 = w00 * gx, w001 = w00 * fx;
        const float w010 = w01 * gx, w011 = w01 * fx;
        const float w100 = w10 * gx, w101 = w10 * fx;
        const float w110 = w11 * gx, w111 = w11 * fx;

        const int z0l = z0 - z_lo;        // in-tile: [0, SZ-2]
        const int y0l = y0 - y_lo;        // in-tile: [0, SY-2]
        const int x0l = x0 - x_al;        // in-tile: [1, SXP-2]

        float a0, a1;

        if (((unsigned)z0l <= (unsigned)(SZ - 2)) &
            ((unsigned)y0l <= (unsigned)(SY - 2)) &
            ((unsigned)(x0l - 1) <= (unsigned)(SXP - 3))) {
            const __half2* p = smh + (z0l * SY + y0l) * SXP + x0l;
            const float2 c000 = __half22float2(p[0]);
            const float2 c001 = __half22float2(p[1]);
            const float2 c010 = __half22float2(p[SXP]);
            const float2 c011 = __half22float2(p[SXP + 1]);
            const float2 c100 = __half22float2(p[SY * SXP]);
            const float2 c101 = __half22float2(p[SY * SXP + 1]);
            const float2 c110 = __half22float2(p[SY * SXP + SXP]);
            const float2 c111 = __half22float2(p[SY * SXP + SXP + 1]);
            a0 = w000 * c000.x + w001 * c001.x
               + w010 * c010.x + w011 * c011.x
               + w100 * c100.x + w101 * c101.x
               + w110 * c110.x + w111 * c111.x;
            a1 = w000 * c000.y + w001 * c001.y
               + w010 * c010.y + w011 * c011.y
               + w100 * c100.y + w101 * c101.y
               + w110 * c110.y + w111 * c111.y;
        } else {
            // rare fallback: sample escapes tile (|flow| > R) — exact fp32
            a0 = 0.0f; a1 = 0.0f;
            #pragma unroll
            for (int dz = 0; dz < 2; ++dz) {
                const int zi = z0 + dz;
                if ((unsigned)zi >= (unsigned)D) continue;
                const float wz = dz ? fz : gz;
                #pragma unroll
                for (int dy = 0; dy < 2; ++dy) {
                    const int yi = y0 + dy;
                    if ((unsigned)yi >= (unsigned)H) continue;
                    const float wzy = wz * (dy ? fy : gy);
                    #pragma unroll
                    for (int dx = 0; dx < 2; ++dx) {
                        const int xi = x0 + dx;
                        if ((unsigned)xi >= (unsigned)W) continue;
                        const float wgt = wzy * (dx ? fx : gx);
                        const int lin = (zi * H + yi) * W + xi;
                        a0 += wgt * __ldg(s0 + lin);
                        a1 += wgt * __ldg(s1 + lin);
                    }
                }
            }
        }

        __stcs(ob + s,     a0);
        __stcs(ob + s + N, a1);
    }
}

extern "C" void kernel_launch(void* const* d_in, const int* in_sizes, int n_in,
                              void* d_out, int out_size)
{
    const float* src  = (const float*)d_in[0];
    const float* flow = (const float*)d_in[1];
    float* out = (float*)d_out;

    static bool attr_done = false;
    if (!attr_done) {
        cudaFuncSetAttribute(st_v12_kernel,
                             cudaFuncAttributeMaxDynamicSharedMemorySize,
                             SMEM_BYTES);
        attr_done = true;
    }

    dim3 block(TX, TY, 2);                  // 1024 threads
    dim3 grid(W / TX, H / TY, B * NZT);     // 5, 12, 20
    st_v12_kernel<<<grid, block, SMEM_BYTES>>>(src, flow, out);
}